// round 1
// baseline (speedup 1.0000x reference)
#include <cuda_runtime.h>
#include <math.h>

#define B 16
#define CIN 3
#define DIM 128
#define KCODES 512
#define H0 256
#define H1 128
#define H2 64

// d_out layout: [recon | z_e | z_q]
#define OFF_ZE  (B*CIN*H0*H0)                  // 3145728
#define OFF_ZQ  (OFF_ZE + B*DIM*H2*H2)         // 11534336

// scratch (alloc-free rule: device globals)
__device__ float g_h[B*DIM*H1*H1];   // encoder hidden, 128 MB
__device__ float g_g[B*DIM*H1*H1];   // decoder hidden, 128 MB
__device__ float g_cnorm[KCODES];

// ---------------------------------------------------------------------------
// codebook squared norms
// ---------------------------------------------------------------------------
__global__ void knorm_kernel(const float* __restrict__ emb) {
    int k = blockIdx.x * blockDim.x + threadIdx.x;
    if (k < KCODES) {
        const float* e = emb + k * DIM;
        float s = 0.f;
#pragma unroll 8
        for (int d = 0; d < DIM; d++) s += e[d] * e[d];
        g_cnorm[k] = s;
    }
}

// ---------------------------------------------------------------------------
// conv1: x[16,3,256,256] -> h[16,128,128,128], k4 s2 p1, relu
// block = (oy, n); 256 threads = 128 oc x 2 x-halves
// ---------------------------------------------------------------------------
__global__ __launch_bounds__(256) void conv1_kernel(
    const float* __restrict__ x, const float* __restrict__ w) {
    __shared__ float ws[DIM * 48];
    __shared__ float ins[CIN][4][258];
    int n = blockIdx.y, oy = blockIdx.x;
    int tid = threadIdx.x;

    for (int i = tid; i < DIM * 48; i += 256) ws[i] = w[i];
    int iy_base = oy * 2 - 1;
    for (int i = tid; i < CIN * 4 * 258; i += 256) {
        int ic = i / 1032; int rem = i - ic * 1032;
        int r = rem / 258; int c = rem - r * 258;
        int iy = iy_base + r, ix = c - 1;
        float v = 0.f;
        if ((unsigned)iy < H0 && (unsigned)ix < H0)
            v = x[((n * CIN + ic) * H0 + iy) * H0 + ix];
        ins[ic][r][c] = v;
    }
    __syncthreads();

    int oc = tid >> 1, half = tid & 1;
    float wr[48];
#pragma unroll
    for (int k = 0; k < 48; k++) wr[k] = ws[oc * 48 + k];

    float* outp = g_h + ((n * DIM + oc) * H1 + oy) * H1;
    for (int ox = half * 64; ox < half * 64 + 64; ox++) {
        float acc = 0.f;
#pragma unroll
        for (int ic = 0; ic < 3; ic++) {
#pragma unroll
            for (int kh = 0; kh < 4; kh++) {
                const float* rp = &ins[ic][kh][0];
                float2 a0 = *(const float2*)&rp[ox * 2];
                float2 a1 = *(const float2*)&rp[ox * 2 + 2];
                const float* wk = &wr[ic * 16 + kh * 4];
                acc += wk[0] * a0.x + wk[1] * a0.y + wk[2] * a1.x + wk[3] * a1.y;
            }
        }
        outp[ox] = fmaxf(acc, 0.f);
    }
}

// ---------------------------------------------------------------------------
// conv2: h[16,128,128,128] -> z_e[16,128,64,64], k4 s2 p1 (no act)
// block = 8x8 output tile x all 128 oc; thread = 8 oc x 4 ox
// ---------------------------------------------------------------------------
__global__ __launch_bounds__(256) void conv2_kernel(
    const float* __restrict__ w, float* __restrict__ ze) {
    __shared__ float ws[DIM][64];       // [oc][ic_l*16 + kh*4 + kw]
    __shared__ float ins[4][18][21];
    int n = blockIdx.z;
    int oy0 = blockIdx.y * 8, ox0 = blockIdx.x * 8;
    int tid = threadIdx.x;
    int ocg = tid >> 4, pos = tid & 15;
    int oyl = pos >> 1, oxq = pos & 1, oxb = oxq * 4;

    float acc[8][4];
#pragma unroll
    for (int o = 0; o < 8; o++)
#pragma unroll
        for (int j = 0; j < 4; j++) acc[o][j] = 0.f;

    int iy_base = oy0 * 2 - 1, ix_base = ox0 * 2 - 1;

    for (int ic0 = 0; ic0 < DIM; ic0 += 4) {
        __syncthreads();
        for (int i = tid; i < 8192; i += 256) {
            int oc = i >> 6, k = i & 63;
            ws[oc][k] = w[oc * 2048 + ic0 * 16 + k];
        }
        for (int i = tid; i < 4 * 18 * 18; i += 256) {
            int ic = i / 324; int rem = i - ic * 324;
            int r = rem / 18; int c = rem - r * 18;
            int iy = iy_base + r, ix = ix_base + c;
            float v = 0.f;
            if ((unsigned)iy < H1 && (unsigned)ix < H1)
                v = g_h[((n * DIM + ic0 + ic) * H1 + iy) * H1 + ix];
            ins[ic][r][c] = v;
        }
        __syncthreads();
#pragma unroll
        for (int icl = 0; icl < 4; icl++) {
#pragma unroll
            for (int kh = 0; kh < 4; kh++) {
                float iv[4][4];
#pragma unroll
                for (int j = 0; j < 4; j++)
#pragma unroll
                    for (int kw = 0; kw < 4; kw++)
                        iv[j][kw] = ins[icl][oyl * 2 + kh][(oxb + j) * 2 + kw];
                int kbase = icl * 16 + kh * 4;
#pragma unroll
                for (int o = 0; o < 8; o++) {
                    float4 wq = *(const float4*)&ws[ocg * 8 + o][kbase];
#pragma unroll
                    for (int j = 0; j < 4; j++) {
                        acc[o][j] += wq.x * iv[j][0];
                        acc[o][j] += wq.y * iv[j][1];
                        acc[o][j] += wq.z * iv[j][2];
                        acc[o][j] += wq.w * iv[j][3];
                    }
                }
            }
        }
    }
    int oy = oy0 + oyl;
#pragma unroll
    for (int o = 0; o < 8; o++) {
        int oc = ocg * 8 + o;
        float* op = ze + ((n * DIM + oc) * H2 + oy) * H2;
#pragma unroll
        for (int j = 0; j < 4; j++) op[ox0 + oxb + j] = acc[o][j];
    }
}

// ---------------------------------------------------------------------------
// VQ: per 64-vector block: argmin over 512 codes of (||c||^2 - 2 z.c), then
// gather z_q = emb[idx] back into NCHW. Dynamic smem: z[128][64] + c[128][132]
// ---------------------------------------------------------------------------
__global__ __launch_bounds__(256) void vq_kernel(
    const float* __restrict__ ze, const float* __restrict__ emb,
    float* __restrict__ zq) {
    extern __shared__ float sm[];
    float* z_s = sm;                 // [d][64]
    float* c_s = sm + 128 * 64;      // [d][132] (padded)
    __shared__ int idx_s[64];

    int tid = threadIdx.x;
    int v0 = blockIdx.x * 64;
    int b = v0 >> 12;            // 4096 spatial per batch
    int s0 = v0 & 4095;

    for (int i = tid; i < 8192; i += 256) {
        int d = i >> 6, vl = i & 63;
        z_s[d * 64 + vl] = ze[(b * DIM + d) * 4096 + s0 + vl];
    }

    int vg = tid >> 4, cg = tid & 15;   // 16 vec-groups x 16 code-groups
    float minv[4] = {3.0e38f, 3.0e38f, 3.0e38f, 3.0e38f};
    int mini[4] = {0, 0, 0, 0};

    for (int ch = 0; ch < 4; ch++) {
        __syncthreads();
        int cbase = ch * 128;
        for (int i = tid; i < 16384; i += 256) {
            int cl = i >> 7, d = i & 127;
            c_s[d * 132 + cl] = emb[(cbase + cl) * DIM + d];
        }
        __syncthreads();

        float dot[4][8];
#pragma unroll
        for (int v = 0; v < 4; v++)
#pragma unroll
            for (int c = 0; c < 8; c++) dot[v][c] = 0.f;

#pragma unroll 4
        for (int d = 0; d < 128; d++) {
            float4 zv = *(const float4*)&z_s[d * 64 + vg * 4];
            float4 c0 = *(const float4*)&c_s[d * 132 + cg * 8];
            float4 c1 = *(const float4*)&c_s[d * 132 + cg * 8 + 4];
            float zz[4] = {zv.x, zv.y, zv.z, zv.w};
            float cc[8] = {c0.x, c0.y, c0.z, c0.w, c1.x, c1.y, c1.z, c1.w};
#pragma unroll
            for (int v = 0; v < 4; v++)
#pragma unroll
                for (int c = 0; c < 8; c++) dot[v][c] += zz[v] * cc[c];
        }
#pragma unroll
        for (int c = 0; c < 8; c++) {
            int code = cbase + cg * 8 + c;
            float cn = g_cnorm[code];
#pragma unroll
            for (int v = 0; v < 4; v++) {
                float dd = cn - 2.f * dot[v][c];
                if (dd < minv[v]) { minv[v] = dd; mini[v] = code; }
            }
        }
    }

    __syncthreads();
    float* red_d = c_s;                  // reuse
    int* red_i = (int*)(c_s + 1024);
#pragma unroll
    for (int v = 0; v < 4; v++) {
        int vl = vg * 4 + v;
        red_d[vl * 16 + cg] = minv[v];
        red_i[vl * 16 + cg] = mini[v];
    }
    __syncthreads();
    if (tid < 64) {
        float bd = red_d[tid * 16]; int bi = red_i[tid * 16];
        for (int g = 1; g < 16; g++) {
            float d2 = red_d[tid * 16 + g]; int i2 = red_i[tid * 16 + g];
            if (d2 < bd || (d2 == bd && i2 < bi)) { bd = d2; bi = i2; }
        }
        idx_s[tid] = bi;
    }
    __syncthreads();
    for (int i = tid; i < 8192; i += 256) {
        int d = i >> 6, vl = i & 63;
        zq[(b * DIM + d) * 4096 + s0 + vl] = __ldg(&emb[idx_s[vl] * DIM + d]);
    }
}

// ---------------------------------------------------------------------------
// deconv1: z_q[16,128,64,64] -> g[16,128,128,128], transposed k4 s2 p1, relu
// parity trick: out (p,q) uses kh in {a,a+2}, kw in {b,b+2}, a=p&1, b=q&1
// block = 8x8 out tile x 128 oc; thread = 8 oc x 4 q-positions (same parity)
// ---------------------------------------------------------------------------
__global__ __launch_bounds__(256) void deconv1_kernel(
    const float* __restrict__ w, const float* __restrict__ zq) {
    __shared__ float ws[DIM][64];   // [oc][ic_l*16 + kh*4 + kw]
    __shared__ float ins[4][6][8];
    int n = blockIdx.z;
    int p0 = blockIdx.y * 8, q0 = blockIdx.x * 8;
    int tid = threadIdx.x;
    int ocg = tid >> 4, pos = tid & 15;
    int pl = pos >> 1, qp = pos & 1;
    int a = pl & 1;
    int r0l = (pl + a) >> 1;
    int rb = p0 / 2 - 1, cb = q0 / 2 - 1;

    float acc[8][4];
#pragma unroll
    for (int o = 0; o < 8; o++)
#pragma unroll
        for (int j = 0; j < 4; j++) acc[o][j] = 0.f;

    for (int ic0 = 0; ic0 < DIM; ic0 += 4) {
        __syncthreads();
        for (int i = tid; i < 8192; i += 256) {
            int oc = i >> 6, k = i & 63;
            ws[oc][k] = w[oc * 2048 + ic0 * 16 + k];
        }
        for (int i = tid; i < 144; i += 256) {
            int ic = i / 36; int rem = i - ic * 36;
            int r = rem / 6, c = rem - r * 6;
            int rr = rb + r, cc = cb + c;
            float v = 0.f;
            if ((unsigned)rr < H2 && (unsigned)cc < H2)
                v = zq[((n * DIM + ic0 + ic) * H2 + rr) * H2 + cc];
            ins[ic][r][c] = v;
        }
        __syncthreads();
#pragma unroll
        for (int icl = 0; icl < 4; icl++) {
            float rin[2][5];
#pragma unroll
            for (int s = 0; s < 2; s++)
#pragma unroll
                for (int m = 0; m < 5; m++)
                    rin[s][m] = ins[icl][r0l + s][qp + m];
            int kb = icl * 16 + a * 4 + qp;
#pragma unroll
            for (int o = 0; o < 8; o++) {
                const float* wrow = &ws[ocg * 8 + o][kb];
                float w00 = wrow[0];   // kh=a,   kw=b
                float w01 = wrow[2];   // kh=a,   kw=b+2
                float w10 = wrow[8];   // kh=a+2, kw=b
                float w11 = wrow[10];  // kh=a+2, kw=b+2
#pragma unroll
                for (int j = 0; j < 4; j++) {
                    acc[o][j] += w00 * rin[0][j] + w01 * rin[0][j + 1]
                               + w10 * rin[1][j] + w11 * rin[1][j + 1];
                }
            }
        }
    }
    int p = p0 + pl;
#pragma unroll
    for (int o = 0; o < 8; o++) {
        int oc = ocg * 8 + o;
        float* op = g_g + ((n * DIM + oc) * H1 + p) * H1;
#pragma unroll
        for (int j = 0; j < 4; j++) {
            int q = q0 + qp + 2 * j;
            op[q] = fmaxf(acc[o][j], 0.f);
        }
    }
}

// ---------------------------------------------------------------------------
// deconv2: g[16,128,128,128] -> recon[16,3,256,256], transposed k4 s2 p1, tanh
// block = 16x16 out tile x 3 oc; thread = 1 position x 3 oc
// ---------------------------------------------------------------------------
__global__ __launch_bounds__(256) void deconv2_kernel(
    const float* __restrict__ w, float* __restrict__ recon) {
    __shared__ float ws[CIN * DIM * 16];   // full weights, 24 KB
    __shared__ float ins[8][10][12];
    int n = blockIdx.z;
    int p0 = blockIdx.y * 16, q0 = blockIdx.x * 16;
    int tid = threadIdx.x;
    int pl = tid >> 4, ql = tid & 15;
    int a = pl & 1, bb = ql & 1;
    int r0l = (pl + a) >> 1, c0l = (ql + bb) >> 1;
    int rb = p0 / 2 - 1, cb = q0 / 2 - 1;

    for (int i = tid; i < CIN * DIM * 16; i += 256) ws[i] = w[i];

    float acc[3] = {0.f, 0.f, 0.f};
    for (int ic0 = 0; ic0 < DIM; ic0 += 8) {
        __syncthreads();
        for (int i = tid; i < 800; i += 256) {
            int ic = i / 100; int rem = i - ic * 100;
            int r = rem / 10, c = rem - r * 10;
            int rr = rb + r, cc = cb + c;
            float v = 0.f;
            if ((unsigned)rr < H1 && (unsigned)cc < H1)
                v = g_g[((n * DIM + ic0 + ic) * H1 + rr) * H1 + cc];
            ins[ic][r][c] = v;
        }
        __syncthreads();
#pragma unroll
        for (int icl = 0; icl < 8; icl++) {
            float i00 = ins[icl][r0l][c0l],     i01 = ins[icl][r0l][c0l + 1];
            float i10 = ins[icl][r0l + 1][c0l], i11 = ins[icl][r0l + 1][c0l + 1];
            int kb = (ic0 + icl) * 16 + a * 4 + bb;
#pragma unroll
            for (int o = 0; o < 3; o++) {
                const float* wr = &ws[o * 2048 + kb];
                acc[o] += wr[0] * i00 + wr[2] * i01 + wr[8] * i10 + wr[10] * i11;
            }
        }
    }
    int p = p0 + pl, q = q0 + ql;
#pragma unroll
    for (int o = 0; o < 3; o++)
        recon[((n * CIN + o) * H0 + p) * H0 + q] = tanhf(acc[o]);
}

// ---------------------------------------------------------------------------
#define VQ_SMEM ((128 * 64 + 128 * 132) * (int)sizeof(float))   // 100352 B

extern "C" void kernel_launch(void* const* d_in, const int* in_sizes, int n_in,
                              void* d_out, int out_size) {
    const float* x    = (const float*)d_in[0];
    const float* w_e1 = (const float*)d_in[1];
    const float* w_e2 = (const float*)d_in[2];
    const float* emb  = (const float*)d_in[3];
    const float* w_d1 = (const float*)d_in[4];
    const float* w_d2 = (const float*)d_in[5];

    float* out   = (float*)d_out;
    float* recon = out;
    float* ze    = out + OFF_ZE;
    float* zq    = out + OFF_ZQ;

    cudaFuncSetAttribute(vq_kernel, cudaFuncAttributeMaxDynamicSharedMemorySize,
                         VQ_SMEM);

    knorm_kernel<<<2, 256>>>(emb);
    conv1_kernel<<<dim3(H1, B), 256>>>(x, w_e1);
    conv2_kernel<<<dim3(8, 8, B), 256>>>(w_e2, ze);
    vq_kernel<<<1024, 256, VQ_SMEM>>>(ze, emb, zq);
    deconv1_kernel<<<dim3(16, 16, B), 256>>>(w_d1, zq);
    deconv2_kernel<<<dim3(16, 16, B), 256>>>(w_d2, recon);
}